// round 15
// baseline (speedup 1.0000x reference)
#include <cuda_runtime.h>
#include <cuda_bf16.h>
#include <cstdint>

// ---------------- problem constants ----------------
#define Bv    8
#define Nv    2048
#define Dv    1024
#define EOv   4
#define EIv   4
#define Hv    4096
#define CAPO  640
#define CAPI  200
#define NPAIR (EOv*EIv)
#define MROWS (Bv*CAPI)      // 1600
#define BND   (Bv*Nv*Dv)
#define EPSG  1e-9f

// ---------------- device scratch ----------------
__device__ int   g_oi1[Bv*Nv], g_oi2[Bv*Nv];
__device__ float g_og1[Bv*Nv], g_og2[Bv*Nv];
__device__ int   g_op1[Bv*Nv], g_op2[Bv*Nv];
__device__ int   g_slot_tok[EOv][Bv][CAPO];
__device__ float g_slot_w[EOv][Bv][CAPO];
__device__ int   g_ii1[EOv*Bv*CAPO], g_ii2[EOv*Bv*CAPO];
__device__ float g_ig1[EOv*Bv*CAPO], g_ig2[EOv*Bv*CAPO];
__device__ int   g_entf[EOv][Bv][CAPO][2];
__device__ int   g_entc[EOv][Bv][CAPO][2];
__device__ float g_entw[EOv][Bv][CAPO][2];
__device__ int   g_src[NPAIR][MROWS];
__device__ float g_proxyO[Bv*EOv];
__device__ int   g_cntO[Bv*EOv];
__device__ float g_proxyI[EOv*Bv*EIv];
__device__ int   g_cntI[EOv*Bv*EIv];

// bf16 split operands
__device__ __nv_bfloat16 gXh[NPAIR][MROWS][Dv], gXl[NPAIR][MROWS][Dv];
__device__ __nv_bfloat16 gW1h[NPAIR][Hv][Dv],  gW1l[NPAIR][Hv][Dv];   // [n][k]
__device__ __nv_bfloat16 gW2h[NPAIR][Dv][Hv],  gW2l[NPAIR][Dv][Hv];   // [n][k]
__device__ __nv_bfloat16 gHh[NPAIR][MROWS][Hv], gHl[NPAIR][MROWS][Hv];
__device__ float g_Y[NPAIR][MROWS][Dv];

// ---------------- helpers ----------------
__device__ __forceinline__ uint32_t smem_u32(const void* p) {
    uint32_t a;
    asm("{ .reg .u64 t; cvta.to.shared.u64 t, %1; cvt.u32.u64 %0, t; }" : "=r"(a) : "l"(p));
    return a;
}
__device__ __forceinline__ void cp16(uint32_t dst, const void* src) {
    asm volatile("cp.async.cg.shared.global [%0], [%1], 16;" :: "r"(dst), "l"(src));
}
__device__ __forceinline__ void cp_commit() {
    asm volatile("cp.async.commit_group;" ::: "memory");
}
template<int NN>
__device__ __forceinline__ void cp_wait() {
    asm volatile("cp.async.wait_group %0;" :: "n"(NN) : "memory");
}
__device__ __forceinline__ void ldx4(uint32_t* r, uint32_t addr) {
    asm volatile("ldmatrix.sync.aligned.m8n8.x4.shared.b16 {%0,%1,%2,%3}, [%4];"
        : "=r"(r[0]), "=r"(r[1]), "=r"(r[2]), "=r"(r[3]) : "r"(addr));
}
__device__ __forceinline__ void mma16816(float* c, const uint32_t* a, uint32_t b0, uint32_t b1) {
    asm volatile("mma.sync.aligned.m16n8k16.row.col.f32.bf16.bf16.f32 "
        "{%0,%1,%2,%3}, {%4,%5,%6,%7}, {%8,%9}, {%0,%1,%2,%3};"
        : "+f"(c[0]), "+f"(c[1]), "+f"(c[2]), "+f"(c[3])
        : "r"(a[0]), "r"(a[1]), "r"(a[2]), "r"(a[3]), "r"(b0), "r"(b1));
}
__device__ __forceinline__ void split_pair(float a, float b, uint32_t& hp, uint32_t& lp) {
    __nv_bfloat16 h0 = __float2bfloat16(a), h1 = __float2bfloat16(b);
    float l0 = a - __bfloat162float(h0), l1 = b - __bfloat162float(h1);
    __nv_bfloat162 hh; hh.x = h0; hh.y = h1;
    __nv_bfloat162 ll; ll.x = __float2bfloat16(l0); ll.y = __float2bfloat16(l1);
    hp = *(uint32_t*)&hh; lp = *(uint32_t*)&ll;
}

// ---------------- K0: zero accumulators ----------------
__global__ void k_init() {
    int i = threadIdx.x;
    if (i < Bv*EOv)      { g_proxyO[i] = 0.f; g_cntO[i] = 0; }
    if (i < EOv*Bv*EIv)  { g_proxyI[i] = 0.f; g_cntI[i] = 0; }
}

// ---------------- weight transpose tile helper ----------------
__device__ __forceinline__ void tw_tile(const float* __restrict__ Wp,
                                        __nv_bfloat16* __restrict__ Thp,
                                        __nv_bfloat16* __restrict__ Tlp,
                                        int R, int Cn, int r0, int c0, int tid) {
    __shared__ float t[32][33];
    {
        int r = tid >> 3, cq = (tid & 7) * 4;
        float4 v = *(const float4*)(Wp + (size_t)(r0+r)*Cn + c0 + cq);
        t[r][cq+0] = v.x; t[r][cq+1] = v.y; t[r][cq+2] = v.z; t[r][cq+3] = v.w;
    }
    __syncthreads();
    #pragma unroll
    for (int h = 0; h < 2; h++) {
        int col = (tid >> 4) + h*16;
        int q   = tid & 15;
        float v0 = t[2*q][col], v1 = t[2*q+1][col];
        uint32_t hp, lp;
        split_pair(v0, v1, hp, lp);
        *(uint32_t*)(Thp + (size_t)(c0+col)*R + r0 + 2*q) = hp;
        *(uint32_t*)(Tlp + (size_t)(c0+col)*R + r0 + 2*q) = lp;
    }
}

#define TW_TILES_PER (( (Hv/32)*(Dv/32) ))   // 4096 tiles per pair per tensor
#define GATE_BLOCKS  ((Bv*Nv)/8)             // 2048

// ---------------- K1: merged outer gating + weight conversion ----------------
__global__ void k_gate_tw(const float* __restrict__ x, const float* __restrict__ wg,
                          const float* __restrict__ W1, const float* __restrict__ W2) {
    if (blockIdx.x >= GATE_BLOCKS) {
        int bid = blockIdx.x - GATE_BLOCKS;
        int tid = threadIdx.x;
        if (bid < TW_TILES_PER * NPAIR) {
            int t = bid;
            int bx = t % (Hv/32); t /= (Hv/32);
            int by = t % (Dv/32); int pair = t / (Dv/32);
            tw_tile(W1 + (size_t)pair*Dv*Hv,
                    &gW1h[0][0][0] + (size_t)pair*Hv*Dv,
                    &gW1l[0][0][0] + (size_t)pair*Hv*Dv,
                    Dv, Hv, by*32, bx*32, tid);
        } else {
            int t = bid - TW_TILES_PER * NPAIR;
            int bx = t % (Dv/32); t /= (Dv/32);
            int by = t % (Hv/32); int pair = t / (Hv/32);
            tw_tile(W2 + (size_t)pair*Hv*Dv,
                    &gW2h[0][0][0] + (size_t)pair*Dv*Hv,
                    &gW2l[0][0][0] + (size_t)pair*Dv*Hv,
                    Hv, Dv, by*32, bx*32, tid);
        }
        return;
    }
    int t = (blockIdx.x * blockDim.x + threadIdx.x) >> 5;
    int lane = threadIdx.x & 31;
    int b = t / Nv;
    const float* xr = x + (size_t)t * Dv;
    const float4* w4 = (const float4*)wg;
    float a0=0.f,a1=0.f,a2=0.f,a3=0.f;
    for (int j = lane; j < Dv; j += 32) {
        float xv = xr[j]; float4 w = w4[j];
        a0 += xv*w.x; a1 += xv*w.y; a2 += xv*w.z; a3 += xv*w.w;
    }
    #pragma unroll
    for (int off = 16; off > 0; off >>= 1) {
        a0 += __shfl_xor_sync(0xffffffffu, a0, off);
        a1 += __shfl_xor_sync(0xffffffffu, a1, off);
        a2 += __shfl_xor_sync(0xffffffffu, a2, off);
        a3 += __shfl_xor_sync(0xffffffffu, a3, off);
    }
    if (lane == 0) {
        float l[4] = {a0,a1,a2,a3};
        float m = fmaxf(fmaxf(l[0],l[1]), fmaxf(l[2],l[3]));
        float p[4]; float s = 0.f;
        #pragma unroll
        for (int e=0;e<4;e++){ p[e] = expf(l[e]-m); s += p[e]; }
        float inv = 1.f/s;
        #pragma unroll
        for (int e=0;e<4;e++) p[e] *= inv;
        int i1 = 0; float g1 = p[0];
        #pragma unroll
        for (int e=1;e<4;e++) if (p[e] > g1) { g1 = p[e]; i1 = e; }
        int i2 = -1; float g2 = -1.f;
        #pragma unroll
        for (int e=0;e<4;e++) if (e != i1 && p[e] > g2) { g2 = p[e]; i2 = e; }
        float den = g1 + g2 + EPSG;
        g_oi1[t] = i1; g_og1[t] = g1/den;
        g_oi2[t] = i2; g_og2[t] = g2/den;
        #pragma unroll
        for (int e=0;e<4;e++) atomicAdd(&g_proxyO[b*EOv+e], p[e]);
        atomicAdd(&g_cntO[b*EOv+i1], 1);
    }
}

// ---------------- K2: outer capacity scan (parallel hierarchical) ----------------
__global__ void k_outer_scan() {
    __shared__ int scnt1[8][4], scnt2[8][4];
    int b = blockIdx.x;
    int tid = threadIdx.x, w = tid >> 5, lane = tid & 31;
    for (int i = tid; i < EOv*CAPO; i += 256) {
        int e = i / CAPO, c = i - e*CAPO;
        g_slot_tok[e][b][c] = -1; g_slot_w[e][b][c] = 0.f;
    }
    unsigned lt = (1u << lane) - 1u;
    int e1v[8], p1v[8];
    int cnt1[4] = {0,0,0,0};
    #pragma unroll
    for (int it = 0; it < 8; it++) {
        int n = w*256 + it*32 + lane;
        int e1 = g_oi1[b*Nv + n];
        e1v[it] = e1;
        int pos = 0;
        #pragma unroll
        for (int e=0;e<4;e++) {
            unsigned mb = __ballot_sync(0xffffffffu, e1 == e);
            if (e1 == e) pos = cnt1[e] + __popc(mb & lt);
            cnt1[e] += __popc(mb);
        }
        p1v[it] = pos;
    }
    if (lane < 4) scnt1[w][lane] = cnt1[lane];
    __syncthreads();
    int base1[4], tot1[4];
    #pragma unroll
    for (int e=0;e<4;e++) {
        int bs = 0, ts = 0;
        #pragma unroll
        for (int ww=0; ww<8; ww++) { int v = scnt1[ww][e]; if (ww < w) bs += v; ts += v; }
        base1[e] = bs; tot1[e] = ts;
    }
    #pragma unroll
    for (int it = 0; it < 8; it++) {
        int n = w*256 + it*32 + lane, t = b*Nv + n;
        int e1 = e1v[it];
        int pos = base1[e1] + p1v[it];
        bool keep = pos < CAPO;
        g_op1[t] = keep ? pos : -1;
        if (keep) { g_slot_tok[e1][b][pos] = n; g_slot_w[e1][b][pos] = g_og1[t]; }
    }
    int kept1[4];
    #pragma unroll
    for (int e=0;e<4;e++) kept1[e] = min(tot1[e], CAPO);
    int e2v[8], p2v[8];
    int cnt2[4] = {0,0,0,0};
    #pragma unroll
    for (int it = 0; it < 8; it++) {
        int n = w*256 + it*32 + lane;
        int e2 = g_oi2[b*Nv + n];
        e2v[it] = e2;
        int pos = 0;
        #pragma unroll
        for (int e=0;e<4;e++) {
            unsigned mb = __ballot_sync(0xffffffffu, e2 == e);
            if (e2 == e) pos = cnt2[e] + __popc(mb & lt);
            cnt2[e] += __popc(mb);
        }
        p2v[it] = pos;
    }
    if (lane < 4) scnt2[w][lane] = cnt2[lane];
    __syncthreads();
    int base2[4];
    #pragma unroll
    for (int e=0;e<4;e++) {
        int bs = 0;
        #pragma unroll
        for (int ww=0; ww<8; ww++) if (ww < w) bs += scnt2[ww][e];
        base2[e] = bs;
    }
    #pragma unroll
    for (int it = 0; it < 8; it++) {
        int n = w*256 + it*32 + lane, t = b*Nv + n;
        int e2 = e2v[it];
        int pos = kept1[e2] + base2[e2] + p2v[it];
        bool keep = pos < CAPO;
        g_op2[t] = keep ? pos : -1;
        if (keep) { g_slot_tok[e2][b][pos] = n; g_slot_w[e2][b][pos] = g_og2[t]; }
    }
}

// ---------------- K3: inner gating (R9 scalar form — known best) ----------------
__global__ void k_inner_gate(const float* __restrict__ x, const float* __restrict__ wgi) {
    int s = (blockIdx.x * blockDim.x + threadIdx.x) >> 5;
    int lane = threadIdx.x & 31;
    if (s >= EOv*Bv*CAPO) return;
    int e = s / (Bv*CAPO); int rem = s - e*Bv*CAPO;
    int b = rem / CAPO;    int co = rem - b*CAPO;
    int tok = g_slot_tok[e][b][co];
    if (tok < 0) { if (lane == 0) { g_ii1[s] = -1; g_ii2[s] = -1; } return; }
    const float* xr = x + ((size_t)b*Nv + tok) * Dv;
    const float4* w4 = (const float4*)(wgi + (size_t)e * Dv * EIv);
    float a0=0.f,a1=0.f,a2=0.f,a3=0.f;
    for (int j = lane; j < Dv; j += 32) {
        float xv = xr[j]; float4 w = w4[j];
        a0 += xv*w.x; a1 += xv*w.y; a2 += xv*w.z; a3 += xv*w.w;
    }
    #pragma unroll
    for (int off = 16; off > 0; off >>= 1) {
        a0 += __shfl_xor_sync(0xffffffffu, a0, off);
        a1 += __shfl_xor_sync(0xffffffffu, a1, off);
        a2 += __shfl_xor_sync(0xffffffffu, a2, off);
        a3 += __shfl_xor_sync(0xffffffffu, a3, off);
    }
    if (lane == 0) {
        float l[4] = {a0,a1,a2,a3};
        float m = fmaxf(fmaxf(l[0],l[1]), fmaxf(l[2],l[3]));
        float p[4]; float ssum = 0.f;
        #pragma unroll
        for (int g=0; g<4; g++){ p[g] = expf(l[g]-m); ssum += p[g]; }
        float inv = 1.f/ssum;
        #pragma unroll
        for (int g=0; g<4; g++) p[g] *= inv;
        int i1 = 0; float g1 = p[0];
        #pragma unroll
        for (int g=1; g<4; g++) if (p[g] > g1) { g1 = p[g]; i1 = g; }
        int i2 = -1; float g2 = -1.f;
        #pragma unroll
        for (int g=0; g<4; g++) if (g != i1 && p[g] > g2) { g2 = p[g]; i2 = g; }
        float w = g_slot_w[e][b][co];
        if (w > 0.5f) {
            float den = g1 + g2 + EPSG;
            g_ii1[s] = i1; g_ig1[s] = g1/den;
            g_ii2[s] = i2; g_ig2[s] = g2/den;
            int base = (e*Bv + b) * EIv;
            #pragma unroll
            for (int g=0; g<4; g++) atomicAdd(&g_proxyI[base+g], p[g]);
            atomicAdd(&g_cntI[base+i1], 1);
        } else {
            g_ii1[s] = -1;
            g_ii2[s] = i1; g_ig2[s] = g1/(g1 + EPSG);
        }
    }
}

// ---------------- K4: inner capacity scan (parallel hierarchical) ----------------
__global__ void k_inner_scan() {
    __shared__ int scnt1[5][4], scnt2[5][4];
    int eb = blockIdx.x; int e = eb / Bv, b = eb - e*Bv;
    int tid = threadIdx.x, w = tid >> 5, lane = tid & 31;
    for (int i = tid; i < EIv*CAPI; i += 160) {
        int f = i / CAPI, ci = i - f*CAPI;
        g_src[e*EIv+f][b*CAPI+ci] = -1;
    }
    for (int i = tid; i < CAPO; i += 160) {
        g_entf[e][b][i][0] = -1; g_entf[e][b][i][1] = -1;
    }
    unsigned lt = (1u << lane) - 1u;
    int f1v[4], p1v[4];
    int cnt1[4] = {0,0,0,0};
    #pragma unroll
    for (int it = 0; it < 4; it++) {
        int co = w*128 + it*32 + lane;
        int s  = (e*Bv + b)*CAPO + co;
        int f1 = g_ii1[s];
        f1v[it] = f1;
        int pos = 0;
        #pragma unroll
        for (int f=0; f<4; f++) {
            unsigned mb = __ballot_sync(0xffffffffu, f1 == f);
            if (f1 == f) pos = cnt1[f] + __popc(mb & lt);
            cnt1[f] += __popc(mb);
        }
        p1v[it] = pos;
    }
    if (lane < 4) scnt1[w][lane] = cnt1[lane];
    __syncthreads();
    int base1[4], tot1[4];
    #pragma unroll
    for (int f=0; f<4; f++) {
        int bs = 0, ts = 0;
        #pragma unroll
        for (int ww=0; ww<5; ww++) { int v = scnt1[ww][f]; if (ww < w) bs += v; ts += v; }
        base1[f] = bs; tot1[f] = ts;
    }
    #pragma unroll
    for (int it = 0; it < 4; it++) {
        int co = w*128 + it*32 + lane;
        int s  = (e*Bv + b)*CAPO + co;
        int f1 = f1v[it];
        if (f1 >= 0) {
            int pos = base1[f1] + p1v[it];
            if (pos < CAPI) {
                g_src[e*EIv+f1][b*CAPI+pos] = g_slot_tok[e][b][co];
                g_entf[e][b][co][0] = f1;
                g_entc[e][b][co][0] = pos;
                g_entw[e][b][co][0] = g_ig1[s];
            }
        }
    }
    int kept1[4];
    #pragma unroll
    for (int f=0; f<4; f++) kept1[f] = min(tot1[f], CAPI);
    int f2v[4], p2v[4];
    int cnt2[4] = {0,0,0,0};
    #pragma unroll
    for (int it = 0; it < 4; it++) {
        int co = w*128 + it*32 + lane;
        int s  = (e*Bv + b)*CAPO + co;
        int f2 = g_ii2[s];
        f2v[it] = f2;
        int pos = 0;
        #pragma unroll
        for (int f=0; f<4; f++) {
            unsigned mb = __ballot_sync(0xffffffffu, f2 == f);
            if (f2 == f) pos = cnt2[f] + __popc(mb & lt);
            cnt2[f] += __popc(mb);
        }
        p2v[it] = pos;
    }
    if (lane < 4) scnt2[w][lane] = cnt2[lane];
    __syncthreads();
    int base2[4];
    #pragma unroll
    for (int f=0; f<4; f++) {
        int bs = 0;
        #pragma unroll
        for (int ww=0; ww<5; ww++) if (ww < w) bs += scnt2[ww][f];
        base2[f] = bs;
    }
    #pragma unroll
    for (int it = 0; it < 4; it++) {
        int co = w*128 + it*32 + lane;
        int s  = (e*Bv + b)*CAPO + co;
        int f2 = f2v[it];
        if (f2 >= 0) {
            int pos = kept1[f2] + base2[f2] + p2v[it];
            if (pos < CAPI) {
                g_src[e*EIv+f2][b*CAPI+pos] = g_slot_tok[e][b][co];
                g_entf[e][b][co][1] = f2;
                g_entc[e][b][co][1] = pos;
                g_entw[e][b][co][1] = g_ig2[s];
            }
        }
    }
}

// ---------------- K5: gather input rows as bf16 hi/lo ----------------
__global__ void k_gather(const float* __restrict__ x) {
    int row = blockIdx.x;
    int pair = row / MROWS; int r = row - pair*MROWS;
    int tok = g_src[pair][r];
    uint2* dh = (uint2*)&gXh[pair][r][0];
    uint2* dl = (uint2*)&gXl[pair][r][0];
    int j = threadIdx.x;
    if (tok < 0) {
        dh[j] = make_uint2(0u,0u); dl[j] = make_uint2(0u,0u);
    } else {
        int b = r / CAPI;
        float4 v = ((const float4*)(x + ((size_t)b*Nv + tok)*Dv))[j];
        uint2 h, l;
        split_pair(v.x, v.y, h.x, l.x);
        split_pair(v.z, v.w, h.y, l.y);
        dh[j] = h; dl[j] = l;
    }
}

// ---------------- K7: mma.sync bf16 fused-split GEMM, M-tile templated ----------------
// MT=128 for GEMM1 (few waves, tail small); MT=64 for GEMM2 (tail 5.6 -> 10.8 waves).
#define PADK   40
#define STRB   (PADK*2)             // 80 bytes per row
#define NSTG   3
#define SMEM_REQ (3*61440)          // worst case (MT=128)

template<int MT, bool L1>
__global__ void __launch_bounds__(256, 1) k_hmma() {
    constexpr int KTOT = L1 ? Dv : Hv;
    constexpr int NTOT = L1 ? Hv : Dv;
    constexpr int NCH  = KTOT / 32;
    constexpr int MI   = MT / 32;            // per-warp 16-row sub-tiles
    constexpr int A_LO = MT * STRB;
    constexpr int B_HI = 2 * MT * STRB;
    constexpr int B_LO = B_HI + 256 * STRB;
    constexpr int STG  = (2*MT + 512) * STRB;

    extern __shared__ char smem[];
    const uint32_t sb = smem_u32(smem);
    const int tid = threadIdx.x, wid = tid >> 5, lane = tid & 31;
    const int pair = blockIdx.z;
    const int m0 = blockIdx.y * MT, n0 = blockIdx.x * 256;
    const int wm = wid & 1, wn = wid >> 1;

    const __nv_bfloat16* Ah = (L1 ? &gXh[0][0][0] : &gHh[0][0][0]) + (size_t)pair*MROWS*KTOT;
    const __nv_bfloat16* Al = (L1 ? &gXl[0][0][0] : &gHl[0][0][0]) + (size_t)pair*MROWS*KTOT;
    const __nv_bfloat16* Bh = (L1 ? &gW1h[0][0][0] : &gW2h[0][0][0]) + (size_t)pair*NTOT*KTOT + (size_t)n0*KTOT;
    const __nv_bfloat16* Bl = (L1 ? &gW1l[0][0][0] : &gW2l[0][0][0]) + (size_t)pair*NTOT*KTOT + (size_t)n0*KTOT;

    float acc[MI][8][4];
    #pragma unroll
    for (int i=0;i<MI;i++)
        #pragma unroll
        for (int j=0;j<8;j++)
            #pragma unroll
            for (int q=0;q<4;q++) acc[i][j][q] = 0.f;

    auto load_stage = [&](int s, int c) {
        const int kof = c * 32;
        const uint32_t st = sb + s*STG;
        #pragma unroll
        for (int u = 0; u < MT/64; u++) {       // A hi+lo: MT*4 16B chunks
            int i = tid + u*256;
            int r = i >> 2, q = i & 3;
            int row = m0 + r; if (row > MROWS-1) row = MROWS-1;
            size_t off = (size_t)row*KTOT + kof + q*8;
            uint32_t d = st + r*STRB + q*16;
            cp16(d,        Ah + off);
            cp16(d + A_LO, Al + off);
        }
        #pragma unroll
        for (int u = 0; u < 4; u++) {           // B hi+lo: 1024 16B chunks
            int i = tid + u*256;
            int r = i >> 2, q = i & 3;
            size_t off = (size_t)r*KTOT + kof + q*8;
            uint32_t d = st + B_HI + r*STRB + q*16;
            cp16(d,                 Bh + off);
            cp16(d + (B_LO - B_HI), Bl + off);
        }
        cp_commit();
    };

    load_stage(0, 0);
    load_stage(1, 1);

    const int lr = lane & 15, lc = (lane >> 4) << 3;
    const uint32_t aoff = ((wm*(MT/2) + lr)*PADK + lc)*2;
    const uint32_t boff = ((wn*64 + lr)*PADK + lc)*2;

    int s = 0;
    for (int c = 0; c < NCH; c++) {
        cp_wait<1>();
        __syncthreads();

        if (c + 2 < NCH) {
            int s2 = s + 2; if (s2 >= NSTG) s2 -= NSTG;
            load_stage(s2, c + 2);
        }

        const uint32_t base = sb + s*STG;
        const uint32_t aHi = base + aoff;
        const uint32_t aLo = aHi + A_LO;
        const uint32_t bHi = base + B_HI + boff;
        const uint32_t bLo = bHi + (B_LO - B_HI);

        #pragma unroll
        for (int j = 0; j < 2; j++) {
            uint32_t af[MI][4], bh[4][4], bl[4][4];
            #pragma unroll
            for (int mi = 0; mi < MI; mi++) ldx4(af[mi], aHi + mi*16*STRB + j*32);
            #pragma unroll
            for (int nb = 0; nb < 4; nb++) ldx4(bh[nb], bHi + nb*16*STRB + j*32);
            #pragma unroll
            for (int nb = 0; nb < 4; nb++) ldx4(bl[nb], bLo + nb*16*STRB + j*32);
            #pragma unroll
            for (int mi = 0; mi < MI; mi++)
                #pragma unroll
                for (int ni = 0; ni < 8; ni++) {
                    int nb = ni >> 1, u = ni & 1;
                    mma16816(acc[mi][ni], af[mi], bh[nb][u], bh[nb][u+2]);
                }
            #pragma unroll
            for (int mi = 0; mi < MI; mi++)
                #pragma unroll
                for (int ni = 0; ni < 8; ni++) {
                    int nb = ni >> 1, u = ni & 1;
                    mma16816(acc[mi][ni], af[mi], bl[nb][u], bl[nb][u+2]);
                }
            #pragma unroll
            for (int mi = 0; mi < MI; mi++) ldx4(af[mi], aLo + mi*16*STRB + j*32);
            #pragma unroll
            for (int mi = 0; mi < MI; mi++)
                #pragma unroll
                for (int ni = 0; ni < 8; ni++) {
                    int nb = ni >> 1, u = ni & 1;
                    mma16816(acc[mi][ni], af[mi], bh[nb][u], bh[nb][u+2]);
                }
        }
        if (++s == NSTG) s = 0;
    }

    int rbase = m0 + wm*(MT/2) + (lane >> 2);
    int cbase = n0 + wn*64 + (lane & 3)*2;
    #pragma unroll
    for (int mi = 0; mi < MI; mi++) {
        #pragma unroll
        for (int half = 0; half < 2; half++) {
            int grow = rbase + mi*16 + half*8;
            if (grow >= MROWS) continue;
            if (L1) {
                uint32_t* oh = (uint32_t*)(&gHh[0][0][0] + ((size_t)pair*MROWS + grow)*NTOT);
                uint32_t* ol = (uint32_t*)(&gHl[0][0][0] + ((size_t)pair*MROWS + grow)*NTOT);
                #pragma unroll
                for (int ni = 0; ni < 8; ni++) {
                    float v0 = fmaxf(acc[mi][ni][half*2],   0.f);
                    float v1 = fmaxf(acc[mi][ni][half*2+1], 0.f);
                    uint32_t hp, lp;
                    split_pair(v0, v1, hp, lp);
                    int col = cbase + ni*8;
                    oh[col >> 1] = hp;
                    ol[col >> 1] = lp;
                }
            } else {
                float* oy = &g_Y[0][0][0] + ((size_t)pair*MROWS + grow)*NTOT;
                #pragma unroll
                for (int ni = 0; ni < 8; ni++) {
                    int col = cbase + ni*8;
                    *(float2*)(oy + col) = make_float2(acc[mi][ni][half*2], acc[mi][ni][half*2+1]);
                }
            }
        }
    }
}

// ---------------- K8: final combine ----------------
__global__ void k_combine(float* __restrict__ out) {
    __shared__ int   sp[4], sr[4];
    __shared__ float sw[4];
    __shared__ int   sc;
    int t = blockIdx.x; int b = t / Nv;
    if (threadIdx.x == 0) {
        int c = 0;
        #pragma unroll
        for (int ch = 0; ch < 2; ch++) {
            int pos = ch ? g_op2[t] : g_op1[t];
            if (pos >= 0) {
                int   e  = ch ? g_oi2[t] : g_oi1[t];
                float wo = ch ? g_og2[t] : g_og1[t];
                #pragma unroll
                for (int j = 0; j < 2; j++) {
                    int f = g_entf[e][b][pos][j];
                    if (f >= 0) {
                        sp[c] = e*EIv + f;
                        sr[c] = b*CAPI + g_entc[e][b][pos][j];
                        sw[c] = wo * g_entw[e][b][pos][j];
                        c++;
                    }
                }
            }
        }
        sc = c;
    }
    __syncthreads();
    int d4 = threadIdx.x;
    float4 acc = make_float4(0.f,0.f,0.f,0.f);
    int cnt = sc;
    for (int k = 0; k < cnt; k++) {
        float4 v = ((const float4*)g_Y[sp[k]][sr[k]])[d4];
        float w = sw[k];
        acc.x += w*v.x; acc.y += w*v.y; acc.z += w*v.z; acc.w += w*v.w;
    }
    ((float4*)(out + (size_t)t*Dv))[d4] = acc;
}

// ---------------- K9: aux loss ----------------
__global__ void k_loss(float* __restrict__ out, int out_size) {
    if (out_size <= BND) return;
    float lo = 0.f;
    for (int i = 0; i < Bv*EOv; i++)
        lo += (g_proxyO[i] / (float)Nv) * ((float)g_cntO[i] / (float)Nv);
    lo = lo / (float)(Bv*EOv) * (float)(EOv*EOv);
    float li = 0.f;
    for (int i = 0; i < EOv*Bv*EIv; i++)
        li += (g_proxyI[i] / (float)CAPO) * ((float)g_cntI[i] / (float)CAPO);
    li = li / (float)(EOv*Bv*EIv) * (float)(EIv*EIv);
    out[BND] = (lo + li) * 0.01f;
}

// ---------------- launch ----------------
extern "C" void kernel_launch(void* const* d_in, const int* in_sizes, int n_in,
                              void* d_out, int out_size) {
    const float* x   = (const float*)d_in[0];
    const float* wgo = (const float*)d_in[1];
    const float* wgi = (const float*)d_in[2];
    const float* w1  = (const float*)d_in[3];
    const float* w2  = (const float*)d_in[4];
    float* out = (float*)d_out;

    cudaFuncSetAttribute(k_hmma<128,true>, cudaFuncAttributeMaxDynamicSharedMemorySize, SMEM_REQ);
    cudaFuncSetAttribute(k_hmma<64,false>, cudaFuncAttributeMaxDynamicSharedMemorySize, SMEM_REQ);

    k_init<<<1, 256>>>();
    k_gate_tw<<<GATE_BLOCKS + 2*TW_TILES_PER*NPAIR, 256>>>(x, wgo, w1, w2);

    k_outer_scan<<<Bv, 256>>>();
    k_inner_gate<<<(EOv*Bv*CAPO)/8, 256>>>(x, wgi);
    k_inner_scan<<<EOv*Bv, 160>>>();
    k_gather<<<NPAIR*MROWS, 256>>>(x);

    // GEMM1: M-tile 128 (13 waves-ish, small tail). GEMM2: M-tile 64 (tail shrinks 4x).
    k_hmma<128,true ><<<dim3(Hv/256, (MROWS+127)/128, NPAIR), 256, 3*((2*128+512)*STRB)>>>();
    k_hmma<64, false><<<dim3(Dv/256, MROWS/64,        NPAIR), 256, 3*((2*64 +512)*STRB)>>>();

    k_combine<<<Bv*Nv, 256>>>(out);
    k_loss<<<1, 1>>>(out, out_size);
}

// round 17
// speedup vs baseline: 1.0378x; 1.0378x over previous
#include <cuda_runtime.h>
#include <cuda_bf16.h>
#include <cstdint>

// ---------------- problem constants ----------------
#define Bv    8
#define Nv    2048
#define Dv    1024
#define EOv   4
#define EIv   4
#define Hv    4096
#define CAPO  640
#define CAPI  200
#define NPAIR (EOv*EIv)
#define MROWS (Bv*CAPI)      // 1600
#define BND   (Bv*Nv*Dv)
#define EPSG  1e-9f

// ---------------- device scratch ----------------
__device__ int   g_oi1[Bv*Nv], g_oi2[Bv*Nv];
__device__ float g_og1[Bv*Nv], g_og2[Bv*Nv];
__device__ int   g_op1[Bv*Nv], g_op2[Bv*Nv];
__device__ int   g_slot_tok[EOv][Bv][CAPO];
__device__ float g_slot_w[EOv][Bv][CAPO];
__device__ int   g_ii1[EOv*Bv*CAPO], g_ii2[EOv*Bv*CAPO];
__device__ float g_ig1[EOv*Bv*CAPO], g_ig2[EOv*Bv*CAPO];
__device__ int   g_entf[EOv][Bv][CAPO][2];
__device__ int   g_entc[EOv][Bv][CAPO][2];
__device__ float g_entw[EOv][Bv][CAPO][2];
__device__ int   g_src[NPAIR][MROWS];
__device__ float g_proxyO[Bv*EOv];
__device__ int   g_cntO[Bv*EOv];
__device__ float g_proxyI[EOv*Bv*EIv];
__device__ int   g_cntI[EOv*Bv*EIv];

// bf16 split operands
__device__ __nv_bfloat16 gXh[NPAIR][MROWS][Dv], gXl[NPAIR][MROWS][Dv];
__device__ __nv_bfloat16 gW1h[NPAIR][Hv][Dv],  gW1l[NPAIR][Hv][Dv];   // [n][k]
__device__ __nv_bfloat16 gW2h[NPAIR][Dv][Hv],  gW2l[NPAIR][Dv][Hv];   // [n][k]
__device__ __nv_bfloat16 gHh[NPAIR][MROWS][Hv], gHl[NPAIR][MROWS][Hv];
__device__ float g_Y[NPAIR][MROWS][Dv];

// ---------------- helpers ----------------
__device__ __forceinline__ uint32_t smem_u32(const void* p) {
    uint32_t a;
    asm("{ .reg .u64 t; cvta.to.shared.u64 t, %1; cvt.u32.u64 %0, t; }" : "=r"(a) : "l"(p));
    return a;
}
__device__ __forceinline__ void cp16(uint32_t dst, const void* src) {
    asm volatile("cp.async.cg.shared.global [%0], [%1], 16;" :: "r"(dst), "l"(src));
}
__device__ __forceinline__ void cp_commit() {
    asm volatile("cp.async.commit_group;" ::: "memory");
}
template<int NN>
__device__ __forceinline__ void cp_wait() {
    asm volatile("cp.async.wait_group %0;" :: "n"(NN) : "memory");
}
__device__ __forceinline__ void ldx4(uint32_t* r, uint32_t addr) {
    asm volatile("ldmatrix.sync.aligned.m8n8.x4.shared.b16 {%0,%1,%2,%3}, [%4];"
        : "=r"(r[0]), "=r"(r[1]), "=r"(r[2]), "=r"(r[3]) : "r"(addr));
}
__device__ __forceinline__ void mma16816(float* c, const uint32_t* a, uint32_t b0, uint32_t b1) {
    asm volatile("mma.sync.aligned.m16n8k16.row.col.f32.bf16.bf16.f32 "
        "{%0,%1,%2,%3}, {%4,%5,%6,%7}, {%8,%9}, {%0,%1,%2,%3};"
        : "+f"(c[0]), "+f"(c[1]), "+f"(c[2]), "+f"(c[3])
        : "r"(a[0]), "r"(a[1]), "r"(a[2]), "r"(a[3]), "r"(b0), "r"(b1));
}
__device__ __forceinline__ void split_pair(float a, float b, uint32_t& hp, uint32_t& lp) {
    __nv_bfloat16 h0 = __float2bfloat16(a), h1 = __float2bfloat16(b);
    float l0 = a - __bfloat162float(h0), l1 = b - __bfloat162float(h1);
    __nv_bfloat162 hh; hh.x = h0; hh.y = h1;
    __nv_bfloat162 ll; ll.x = __float2bfloat16(l0); ll.y = __float2bfloat16(l1);
    hp = *(uint32_t*)&hh; lp = *(uint32_t*)&ll;
}

// ---------------- K0: zero accumulators ----------------
__global__ void k_init() {
    int i = threadIdx.x;
    if (i < Bv*EOv)      { g_proxyO[i] = 0.f; g_cntO[i] = 0; }
    if (i < EOv*Bv*EIv)  { g_proxyI[i] = 0.f; g_cntI[i] = 0; }
}

// ---------------- weight transpose tile helper ----------------
__device__ __forceinline__ void tw_tile(const float* __restrict__ Wp,
                                        __nv_bfloat16* __restrict__ Thp,
                                        __nv_bfloat16* __restrict__ Tlp,
                                        int R, int Cn, int r0, int c0, int tid) {
    __shared__ float t[32][33];
    {
        int r = tid >> 3, cq = (tid & 7) * 4;
        float4 v = *(const float4*)(Wp + (size_t)(r0+r)*Cn + c0 + cq);
        t[r][cq+0] = v.x; t[r][cq+1] = v.y; t[r][cq+2] = v.z; t[r][cq+3] = v.w;
    }
    __syncthreads();
    #pragma unroll
    for (int h = 0; h < 2; h++) {
        int col = (tid >> 4) + h*16;
        int q   = tid & 15;
        float v0 = t[2*q][col], v1 = t[2*q+1][col];
        uint32_t hp, lp;
        split_pair(v0, v1, hp, lp);
        *(uint32_t*)(Thp + (size_t)(c0+col)*R + r0 + 2*q) = hp;
        *(uint32_t*)(Tlp + (size_t)(c0+col)*R + r0 + 2*q) = lp;
    }
}

#define TW_TILES_PER (( (Hv/32)*(Dv/32) ))   // 4096 tiles per pair per tensor
#define GATE_BLOCKS  ((Bv*Nv)/8)             // 2048

// ---------------- K1: merged outer gating + weight conversion ----------------
__global__ void k_gate_tw(const float* __restrict__ x, const float* __restrict__ wg,
                          const float* __restrict__ W1, const float* __restrict__ W2) {
    if (blockIdx.x >= GATE_BLOCKS) {
        int bid = blockIdx.x - GATE_BLOCKS;
        int tid = threadIdx.x;
        if (bid < TW_TILES_PER * NPAIR) {
            int t = bid;
            int bx = t % (Hv/32); t /= (Hv/32);
            int by = t % (Dv/32); int pair = t / (Dv/32);
            tw_tile(W1 + (size_t)pair*Dv*Hv,
                    &gW1h[0][0][0] + (size_t)pair*Hv*Dv,
                    &gW1l[0][0][0] + (size_t)pair*Hv*Dv,
                    Dv, Hv, by*32, bx*32, tid);
        } else {
            int t = bid - TW_TILES_PER * NPAIR;
            int bx = t % (Dv/32); t /= (Dv/32);
            int by = t % (Hv/32); int pair = t / (Hv/32);
            tw_tile(W2 + (size_t)pair*Hv*Dv,
                    &gW2h[0][0][0] + (size_t)pair*Dv*Hv,
                    &gW2l[0][0][0] + (size_t)pair*Dv*Hv,
                    Hv, Dv, by*32, bx*32, tid);
        }
        return;
    }
    int t = (blockIdx.x * blockDim.x + threadIdx.x) >> 5;
    int lane = threadIdx.x & 31;
    int b = t / Nv;
    const float* xr = x + (size_t)t * Dv;
    const float4* w4 = (const float4*)wg;
    float a0=0.f,a1=0.f,a2=0.f,a3=0.f;
    for (int j = lane; j < Dv; j += 32) {
        float xv = xr[j]; float4 w = w4[j];
        a0 += xv*w.x; a1 += xv*w.y; a2 += xv*w.z; a3 += xv*w.w;
    }
    #pragma unroll
    for (int off = 16; off > 0; off >>= 1) {
        a0 += __shfl_xor_sync(0xffffffffu, a0, off);
        a1 += __shfl_xor_sync(0xffffffffu, a1, off);
        a2 += __shfl_xor_sync(0xffffffffu, a2, off);
        a3 += __shfl_xor_sync(0xffffffffu, a3, off);
    }
    if (lane == 0) {
        float l[4] = {a0,a1,a2,a3};
        float m = fmaxf(fmaxf(l[0],l[1]), fmaxf(l[2],l[3]));
        float p[4]; float s = 0.f;
        #pragma unroll
        for (int e=0;e<4;e++){ p[e] = expf(l[e]-m); s += p[e]; }
        float inv = 1.f/s;
        #pragma unroll
        for (int e=0;e<4;e++) p[e] *= inv;
        int i1 = 0; float g1 = p[0];
        #pragma unroll
        for (int e=1;e<4;e++) if (p[e] > g1) { g1 = p[e]; i1 = e; }
        int i2 = -1; float g2 = -1.f;
        #pragma unroll
        for (int e=0;e<4;e++) if (e != i1 && p[e] > g2) { g2 = p[e]; i2 = e; }
        float den = g1 + g2 + EPSG;
        g_oi1[t] = i1; g_og1[t] = g1/den;
        g_oi2[t] = i2; g_og2[t] = g2/den;
        #pragma unroll
        for (int e=0;e<4;e++) atomicAdd(&g_proxyO[b*EOv+e], p[e]);
        atomicAdd(&g_cntO[b*EOv+i1], 1);
    }
}

// ---------------- K2: outer capacity scan (parallel hierarchical) ----------------
__global__ void k_outer_scan() {
    __shared__ int scnt1[8][4], scnt2[8][4];
    int b = blockIdx.x;
    int tid = threadIdx.x, w = tid >> 5, lane = tid & 31;
    for (int i = tid; i < EOv*CAPO; i += 256) {
        int e = i / CAPO, c = i - e*CAPO;
        g_slot_tok[e][b][c] = -1; g_slot_w[e][b][c] = 0.f;
    }
    unsigned lt = (1u << lane) - 1u;
    int e1v[8], p1v[8];
    int cnt1[4] = {0,0,0,0};
    #pragma unroll
    for (int it = 0; it < 8; it++) {
        int n = w*256 + it*32 + lane;
        int e1 = g_oi1[b*Nv + n];
        e1v[it] = e1;
        int pos = 0;
        #pragma unroll
        for (int e=0;e<4;e++) {
            unsigned mb = __ballot_sync(0xffffffffu, e1 == e);
            if (e1 == e) pos = cnt1[e] + __popc(mb & lt);
            cnt1[e] += __popc(mb);
        }
        p1v[it] = pos;
    }
    if (lane < 4) scnt1[w][lane] = cnt1[lane];
    __syncthreads();
    int base1[4], tot1[4];
    #pragma unroll
    for (int e=0;e<4;e++) {
        int bs = 0, ts = 0;
        #pragma unroll
        for (int ww=0; ww<8; ww++) { int v = scnt1[ww][e]; if (ww < w) bs += v; ts += v; }
        base1[e] = bs; tot1[e] = ts;
    }
    #pragma unroll
    for (int it = 0; it < 8; it++) {
        int n = w*256 + it*32 + lane, t = b*Nv + n;
        int e1 = e1v[it];
        int pos = base1[e1] + p1v[it];
        bool keep = pos < CAPO;
        g_op1[t] = keep ? pos : -1;
        if (keep) { g_slot_tok[e1][b][pos] = n; g_slot_w[e1][b][pos] = g_og1[t]; }
    }
    int kept1[4];
    #pragma unroll
    for (int e=0;e<4;e++) kept1[e] = min(tot1[e], CAPO);
    int e2v[8], p2v[8];
    int cnt2[4] = {0,0,0,0};
    #pragma unroll
    for (int it = 0; it < 8; it++) {
        int n = w*256 + it*32 + lane;
        int e2 = g_oi2[b*Nv + n];
        e2v[it] = e2;
        int pos = 0;
        #pragma unroll
        for (int e=0;e<4;e++) {
            unsigned mb = __ballot_sync(0xffffffffu, e2 == e);
            if (e2 == e) pos = cnt2[e] + __popc(mb & lt);
            cnt2[e] += __popc(mb);
        }
        p2v[it] = pos;
    }
    if (lane < 4) scnt2[w][lane] = cnt2[lane];
    __syncthreads();
    int base2[4];
    #pragma unroll
    for (int e=0;e<4;e++) {
        int bs = 0;
        #pragma unroll
        for (int ww=0; ww<8; ww++) if (ww < w) bs += scnt2[ww][e];
        base2[e] = bs;
    }
    #pragma unroll
    for (int it = 0; it < 8; it++) {
        int n = w*256 + it*32 + lane, t = b*Nv + n;
        int e2 = e2v[it];
        int pos = kept1[e2] + base2[e2] + p2v[it];
        bool keep = pos < CAPO;
        g_op2[t] = keep ? pos : -1;
        if (keep) { g_slot_tok[e2][b][pos] = n; g_slot_w[e2][b][pos] = g_og2[t]; }
    }
}

// ---------------- K3: inner gating ----------------
__global__ void k_inner_gate(const float* __restrict__ x, const float* __restrict__ wgi) {
    int s = (blockIdx.x * blockDim.x + threadIdx.x) >> 5;
    int lane = threadIdx.x & 31;
    if (s >= EOv*Bv*CAPO) return;
    int e = s / (Bv*CAPO); int rem = s - e*Bv*CAPO;
    int b = rem / CAPO;    int co = rem - b*CAPO;
    int tok = g_slot_tok[e][b][co];
    if (tok < 0) { if (lane == 0) { g_ii1[s] = -1; g_ii2[s] = -1; } return; }
    const float* xr = x + ((size_t)b*Nv + tok) * Dv;
    const float4* w4 = (const float4*)(wgi + (size_t)e * Dv * EIv);
    float a0=0.f,a1=0.f,a2=0.f,a3=0.f;
    for (int j = lane; j < Dv; j += 32) {
        float xv = xr[j]; float4 w = w4[j];
        a0 += xv*w.x; a1 += xv*w.y; a2 += xv*w.z; a3 += xv*w.w;
    }
    #pragma unroll
    for (int off = 16; off > 0; off >>= 1) {
        a0 += __shfl_xor_sync(0xffffffffu, a0, off);
        a1 += __shfl_xor_sync(0xffffffffu, a1, off);
        a2 += __shfl_xor_sync(0xffffffffu, a2, off);
        a3 += __shfl_xor_sync(0xffffffffu, a3, off);
    }
    if (lane == 0) {
        float l[4] = {a0,a1,a2,a3};
        float m = fmaxf(fmaxf(l[0],l[1]), fmaxf(l[2],l[3]));
        float p[4]; float ssum = 0.f;
        #pragma unroll
        for (int g=0; g<4; g++){ p[g] = expf(l[g]-m); ssum += p[g]; }
        float inv = 1.f/ssum;
        #pragma unroll
        for (int g=0; g<4; g++) p[g] *= inv;
        int i1 = 0; float g1 = p[0];
        #pragma unroll
        for (int g=1; g<4; g++) if (p[g] > g1) { g1 = p[g]; i1 = g; }
        int i2 = -1; float g2 = -1.f;
        #pragma unroll
        for (int g=0; g<4; g++) if (g != i1 && p[g] > g2) { g2 = p[g]; i2 = g; }
        float w = g_slot_w[e][b][co];
        if (w > 0.5f) {
            float den = g1 + g2 + EPSG;
            g_ii1[s] = i1; g_ig1[s] = g1/den;
            g_ii2[s] = i2; g_ig2[s] = g2/den;
            int base = (e*Bv + b) * EIv;
            #pragma unroll
            for (int g=0; g<4; g++) atomicAdd(&g_proxyI[base+g], p[g]);
            atomicAdd(&g_cntI[base+i1], 1);
        } else {
            g_ii1[s] = -1;
            g_ii2[s] = i1; g_ig2[s] = g1/(g1 + EPSG);
        }
    }
}

// ---------------- K4: inner capacity scan (parallel hierarchical) ----------------
__global__ void k_inner_scan() {
    __shared__ int scnt1[5][4], scnt2[5][4];
    int eb = blockIdx.x; int e = eb / Bv, b = eb - e*Bv;
    int tid = threadIdx.x, w = tid >> 5, lane = tid & 31;
    for (int i = tid; i < EIv*CAPI; i += 160) {
        int f = i / CAPI, ci = i - f*CAPI;
        g_src[e*EIv+f][b*CAPI+ci] = -1;
    }
    for (int i = tid; i < CAPO; i += 160) {
        g_entf[e][b][i][0] = -1; g_entf[e][b][i][1] = -1;
    }
    unsigned lt = (1u << lane) - 1u;
    int f1v[4], p1v[4];
    int cnt1[4] = {0,0,0,0};
    #pragma unroll
    for (int it = 0; it < 4; it++) {
        int co = w*128 + it*32 + lane;
        int s  = (e*Bv + b)*CAPO + co;
        int f1 = g_ii1[s];
        f1v[it] = f1;
        int pos = 0;
        #pragma unroll
        for (int f=0; f<4; f++) {
            unsigned mb = __ballot_sync(0xffffffffu, f1 == f);
            if (f1 == f) pos = cnt1[f] + __popc(mb & lt);
            cnt1[f] += __popc(mb);
        }
        p1v[it] = pos;
    }
    if (lane < 4) scnt1[w][lane] = cnt1[lane];
    __syncthreads();
    int base1[4], tot1[4];
    #pragma unroll
    for (int f=0; f<4; f++) {
        int bs = 0, ts = 0;
        #pragma unroll
        for (int ww=0; ww<5; ww++) { int v = scnt1[ww][f]; if (ww < w) bs += v; ts += v; }
        base1[f] = bs; tot1[f] = ts;
    }
    #pragma unroll
    for (int it = 0; it < 4; it++) {
        int co = w*128 + it*32 + lane;
        int s  = (e*Bv + b)*CAPO + co;
        int f1 = f1v[it];
        if (f1 >= 0) {
            int pos = base1[f1] + p1v[it];
            if (pos < CAPI) {
                g_src[e*EIv+f1][b*CAPI+pos] = g_slot_tok[e][b][co];
                g_entf[e][b][co][0] = f1;
                g_entc[e][b][co][0] = pos;
                g_entw[e][b][co][0] = g_ig1[s];
            }
        }
    }
    int kept1[4];
    #pragma unroll
    for (int f=0; f<4; f++) kept1[f] = min(tot1[f], CAPI);
    int f2v[4], p2v[4];
    int cnt2[4] = {0,0,0,0};
    #pragma unroll
    for (int it = 0; it < 4; it++) {
        int co = w*128 + it*32 + lane;
        int s  = (e*Bv + b)*CAPO + co;
        int f2 = g_ii2[s];
        f2v[it] = f2;
        int pos = 0;
        #pragma unroll
        for (int f=0; f<4; f++) {
            unsigned mb = __ballot_sync(0xffffffffu, f2 == f);
            if (f2 == f) pos = cnt2[f] + __popc(mb & lt);
            cnt2[f] += __popc(mb);
        }
        p2v[it] = pos;
    }
    if (lane < 4) scnt2[w][lane] = cnt2[lane];
    __syncthreads();
    int base2[4];
    #pragma unroll
    for (int f=0; f<4; f++) {
        int bs = 0;
        #pragma unroll
        for (int ww=0; ww<5; ww++) if (ww < w) bs += scnt2[ww][f];
        base2[f] = bs;
    }
    #pragma unroll
    for (int it = 0; it < 4; it++) {
        int co = w*128 + it*32 + lane;
        int s  = (e*Bv + b)*CAPO + co;
        int f2 = f2v[it];
        if (f2 >= 0) {
            int pos = kept1[f2] + base2[f2] + p2v[it];
            if (pos < CAPI) {
                g_src[e*EIv+f2][b*CAPI+pos] = g_slot_tok[e][b][co];
                g_entf[e][b][co][1] = f2;
                g_entc[e][b][co][1] = pos;
                g_entw[e][b][co][1] = g_ig2[s];
            }
        }
    }
}

// ---------------- K5: gather input rows as bf16 hi/lo ----------------
__global__ void k_gather(const float* __restrict__ x) {
    int row = blockIdx.x;
    int pair = row / MROWS; int r = row - pair*MROWS;
    int tok = g_src[pair][r];
    uint2* dh = (uint2*)&gXh[pair][r][0];
    uint2* dl = (uint2*)&gXl[pair][r][0];
    int j = threadIdx.x;
    if (tok < 0) {
        dh[j] = make_uint2(0u,0u); dl[j] = make_uint2(0u,0u);
    } else {
        int b = r / CAPI;
        float4 v = ((const float4*)(x + ((size_t)b*Nv + tok)*Dv))[j];
        uint2 h, l;
        split_pair(v.x, v.y, h.x, l.x);
        split_pair(v.z, v.w, h.y, l.y);
        dh[j] = h; dl[j] = l;
    }
}

// ---------------- K7: mma.sync bf16 fused-split GEMM (R9 champion, unchanged) ----------------
#define PADK   40
#define STRB   (PADK*2)             // 80 bytes per row
#define A_LO_O 10240                // 128*80
#define B_HI_O 20480
#define B_LO_O 40960
#define STAGE  61440
#define NSTG   3
#define SMEM_REQ (NSTG*STAGE)       // 184320

template<bool L1>
__global__ void __launch_bounds__(256, 1) k_hmma() {
    constexpr int KTOT = L1 ? Dv : Hv;
    constexpr int NTOT = L1 ? Hv : Dv;
    constexpr int NCH  = KTOT / 32;

    extern __shared__ char smem[];
    const uint32_t sb = smem_u32(smem);
    const int tid = threadIdx.x, wid = tid >> 5, lane = tid & 31;
    const int pair = blockIdx.z;
    const int m0 = blockIdx.y * 128, n0 = blockIdx.x * 256;
    const int wm = wid & 1, wn = wid >> 1;

    const __nv_bfloat16* Ah = (L1 ? &gXh[0][0][0] : &gHh[0][0][0]) + (size_t)pair*MROWS*KTOT;
    const __nv_bfloat16* Al = (L1 ? &gXl[0][0][0] : &gHl[0][0][0]) + (size_t)pair*MROWS*KTOT;
    const __nv_bfloat16* Bh = (L1 ? &gW1h[0][0][0] : &gW2h[0][0][0]) + (size_t)pair*NTOT*KTOT + (size_t)n0*KTOT;
    const __nv_bfloat16* Bl = (L1 ? &gW1l[0][0][0] : &gW2l[0][0][0]) + (size_t)pair*NTOT*KTOT + (size_t)n0*KTOT;

    float acc[4][8][4];
    #pragma unroll
    for (int i=0;i<4;i++)
        #pragma unroll
        for (int j=0;j<8;j++)
            #pragma unroll
            for (int q=0;q<4;q++) acc[i][j][q] = 0.f;

    auto load_stage = [&](int s, int c) {
        const int kof = c * 32;
        const uint32_t st = sb + s*STAGE;
        #pragma unroll
        for (int u = 0; u < 2; u++) {           // A hi+lo
            int i = tid + u*256;
            int r = i >> 2, q = i & 3;
            int row = m0 + r; if (row > MROWS-1) row = MROWS-1;
            size_t off = (size_t)row*KTOT + kof + q*8;
            uint32_t d = st + r*STRB + q*16;
            cp16(d,          Ah + off);
            cp16(d + A_LO_O, Al + off);
        }
        #pragma unroll
        for (int u = 0; u < 4; u++) {           // B hi+lo
            int i = tid + u*256;
            int r = i >> 2, q = i & 3;
            size_t off = (size_t)r*KTOT + kof + q*8;
            uint32_t d = st + B_HI_O + r*STRB + q*16;
            cp16(d,                     Bh + off);
            cp16(d + (B_LO_O - B_HI_O), Bl + off);
        }
        cp_commit();
    };

    load_stage(0, 0);
    load_stage(1, 1);

    const int lr = lane & 15, lc = (lane >> 4) << 3;
    const uint32_t aoff = ((wm*64 + lr)*PADK + lc)*2;
    const uint32_t boff = ((wn*64 + lr)*PADK + lc)*2;

    int s = 0;
    for (int c = 0; c < NCH; c++) {
        cp_wait<1>();
        __syncthreads();

        if (c + 2 < NCH) {
            int s2 = s + 2; if (s2 >= NSTG) s2 -= NSTG;
            load_stage(s2, c + 2);
        }

        const uint32_t base = sb + s*STAGE;
        const uint32_t aHi = base + aoff;
        const uint32_t aLo = aHi + A_LO_O;
        const uint32_t bHi = base + B_HI_O + boff;
        const uint32_t bLo = bHi + (B_LO_O - B_HI_O);

        #pragma unroll
        for (int j = 0; j < 2; j++) {
            uint32_t af[4][4], bh[4][4], bl[4][4];
            #pragma unroll
            for (int mi = 0; mi < 4; mi++) ldx4(af[mi], aHi + mi*16*STRB + j*32);
            #pragma unroll
            for (int nb = 0; nb < 4; nb++) ldx4(bh[nb], bHi + nb*16*STRB + j*32);
            #pragma unroll
            for (int nb = 0; nb < 4; nb++) ldx4(bl[nb], bLo + nb*16*STRB + j*32);
            #pragma unroll
            for (int mi = 0; mi < 4; mi++)
                #pragma unroll
                for (int ni = 0; ni < 8; ni++) {
                    int nb = ni >> 1, u = ni & 1;
                    mma16816(acc[mi][ni], af[mi], bh[nb][u], bh[nb][u+2]);
                }
            #pragma unroll
            for (int mi = 0; mi < 4; mi++)
                #pragma unroll
                for (int ni = 0; ni < 8; ni++) {
                    int nb = ni >> 1, u = ni & 1;
                    mma16816(acc[mi][ni], af[mi], bl[nb][u], bl[nb][u+2]);
                }
            #pragma unroll
            for (int mi = 0; mi < 4; mi++) ldx4(af[mi], aLo + mi*16*STRB + j*32);
            #pragma unroll
            for (int mi = 0; mi < 4; mi++)
                #pragma unroll
                for (int ni = 0; ni < 8; ni++) {
                    int nb = ni >> 1, u = ni & 1;
                    mma16816(acc[mi][ni], af[mi], bh[nb][u], bh[nb][u+2]);
                }
        }
        if (++s == NSTG) s = 0;
    }

    int rbase = m0 + wm*64 + (lane >> 2);
    int cbase = n0 + wn*64 + (lane & 3)*2;
    #pragma unroll
    for (int mi = 0; mi < 4; mi++) {
        #pragma unroll
        for (int half = 0; half < 2; half++) {
            int grow = rbase + mi*16 + half*8;
            if (grow >= MROWS) continue;
            if (L1) {
                uint32_t* oh = (uint32_t*)(&gHh[0][0][0] + ((size_t)pair*MROWS + grow)*NTOT);
                uint32_t* ol = (uint32_t*)(&gHl[0][0][0] + ((size_t)pair*MROWS + grow)*NTOT);
                #pragma unroll
                for (int ni = 0; ni < 8; ni++) {
                    float v0 = fmaxf(acc[mi][ni][half*2],   0.f);
                    float v1 = fmaxf(acc[mi][ni][half*2+1], 0.f);
                    uint32_t hp, lp;
                    split_pair(v0, v1, hp, lp);
                    int col = cbase + ni*8;
                    oh[col >> 1] = hp;
                    ol[col >> 1] = lp;
                }
            } else {
                float* oy = &g_Y[0][0][0] + ((size_t)pair*MROWS + grow)*NTOT;
                #pragma unroll
                for (int ni = 0; ni < 8; ni++) {
                    int col = cbase + ni*8;
                    *(float2*)(oy + col) = make_float2(acc[mi][ni][half*2], acc[mi][ni][half*2+1]);
                }
            }
        }
    }
}

// ---------------- K8: final combine (+ aux loss folded into block 0) ----------------
__global__ void k_combine(float* __restrict__ out, int out_size) {
    __shared__ int   sp[4], sr[4];
    __shared__ float sw[4];
    __shared__ int   sc;
    int t = blockIdx.x; int b = t / Nv;
    if (threadIdx.x == 0) {
        int c = 0;
        #pragma unroll
        for (int ch = 0; ch < 2; ch++) {
            int pos = ch ? g_op2[t] : g_op1[t];
            if (pos >= 0) {
                int   e  = ch ? g_oi2[t] : g_oi1[t];
                float wo = ch ? g_og2[t] : g_og1[t];
                #pragma unroll
                for (int j = 0; j < 2; j++) {
                    int f = g_entf[e][b][pos][j];
                    if (f >= 0) {
                        sp[c] = e*EIv + f;
                        sr[c] = b*CAPI + g_entc[e][b][pos][j];
                        sw[c] = wo * g_entw[e][b][pos][j];
                        c++;
                    }
                }
            }
        }
        sc = c;
    } else if (t == 0 && threadIdx.x == 32 && out_size > BND) {
        // aux loss: independent of combine output elements, inputs ready pre-GEMM
        float lo = 0.f;
        for (int i = 0; i < Bv*EOv; i++)
            lo += (g_proxyO[i] / (float)Nv) * ((float)g_cntO[i] / (float)Nv);
        lo = lo / (float)(Bv*EOv) * (float)(EOv*EOv);
        float li = 0.f;
        for (int i = 0; i < EOv*Bv*EIv; i++)
            li += (g_proxyI[i] / (float)CAPO) * ((float)g_cntI[i] / (float)CAPO);
        li = li / (float)(EOv*Bv*EIv) * (float)(EIv*EIv);
        out[BND] = (lo + li) * 0.01f;
    }
    __syncthreads();
    int d4 = threadIdx.x;
    float4 acc = make_float4(0.f,0.f,0.f,0.f);
    int cnt = sc;
    for (int k = 0; k < cnt; k++) {
        float4 v = ((const float4*)g_Y[sp[k]][sr[k]])[d4];
        float w = sw[k];
        acc.x += w*v.x; acc.y += w*v.y; acc.z += w*v.z; acc.w += w*v.w;
    }
    ((float4*)(out + (size_t)t*Dv))[d4] = acc;
}

// ---------------- launch ----------------
extern "C" void kernel_launch(void* const* d_in, const int* in_sizes, int n_in,
                              void* d_out, int out_size) {
    const float* x   = (const float*)d_in[0];
    const float* wgo = (const float*)d_in[1];
    const float* wgi = (const float*)d_in[2];
    const float* w1  = (const float*)d_in[3];
    const float* w2  = (const float*)d_in[4];
    float* out = (float*)d_out;

    cudaFuncSetAttribute(k_hmma<true>,  cudaFuncAttributeMaxDynamicSharedMemorySize, SMEM_REQ);
    cudaFuncSetAttribute(k_hmma<false>, cudaFuncAttributeMaxDynamicSharedMemorySize, SMEM_REQ);

    k_init<<<1, 256>>>();
    k_gate_tw<<<GATE_BLOCKS + 2*TW_TILES_PER*NPAIR, 256>>>(x, wgo, w1, w2);

    k_outer_scan<<<Bv, 256>>>();
    k_inner_gate<<<(EOv*Bv*CAPO)/8, 256>>>(x, wgi);
    k_inner_scan<<<EOv*Bv, 160>>>();
    k_gather<<<NPAIR*MROWS, 256>>>(x);

    k_hmma<true ><<<dim3(Hv/256, (MROWS+127)/128, NPAIR), 256, SMEM_REQ>>>();
    k_hmma<false><<<dim3(Dv/256, (MROWS+127)/128, NPAIR), 256, SMEM_REQ>>>();

    k_combine<<<Bv*Nv, 256>>>(out, out_size);
}